// round 1
// baseline (speedup 1.0000x reference)
#include <cuda_runtime.h>
#include <cstdint>
#include <cstdio>

// Problem geometry (fixed by the reference)
#define D_MODEL 1024
#define N_HEADS 16
#define DK      64
#define BATCH   2
#define SEQ     2048
#define MTOT    (BATCH*SEQ)          // 4096 rows of x flattened

// Scratch: __device__ globals (allocation inside kernel_launch is forbidden)
__device__ float g_Q[(size_t)MTOT * D_MODEL];
__device__ float g_K[(size_t)MTOT * D_MODEL];
__device__ float g_V[(size_t)MTOT * D_MODEL];
__device__ float g_O[(size_t)MTOT * D_MODEL];
// Fallback scores buffer in case d_out does not include the attn_weights region
__device__ float g_S_fallback[(size_t)BATCH * N_HEADS * SEQ * SEQ];

// ---------------------------------------------------------------------------
// Generic NT GEMM: C[m,n] = scale * sum_k A[m,k] * B[n,k]
// 64x64 block tile, BK=16, 256 threads, 4x4 per-thread micro-tile.
// Requires M,N % 64 == 0, K % 16 == 0, all pointers 16B-aligned,
// lda/ldb % 4 == 0.
// ---------------------------------------------------------------------------
__global__ void gemm_nt(const float* __restrict__ A, const float* __restrict__ B,
                        float* __restrict__ C,
                        int K, int lda, int ldb, int ldc, float scale)
{
    __shared__ float As[16][65];
    __shared__ float Bs[16][65];

    const int tid = threadIdx.x;
    const int tx = tid & 15;        // 0..15  (n direction)
    const int ty = tid >> 4;        // 0..15  (m direction)
    const int m0 = blockIdx.y * 64;
    const int n0 = blockIdx.x * 64;

    float acc[4][4] = {};

    const int lr = tid >> 2;        // 0..63 : row within tile
    const int lc = (tid & 3) * 4;   // 0,4,8,12 : col within k-slice

    for (int k0 = 0; k0 < K; k0 += 16) {
        float4 av = *reinterpret_cast<const float4*>(A + (size_t)(m0 + lr) * lda + k0 + lc);
        float4 bv = *reinterpret_cast<const float4*>(B + (size_t)(n0 + lr) * ldb + k0 + lc);
        As[lc + 0][lr] = av.x; As[lc + 1][lr] = av.y; As[lc + 2][lr] = av.z; As[lc + 3][lr] = av.w;
        Bs[lc + 0][lr] = bv.x; Bs[lc + 1][lr] = bv.y; Bs[lc + 2][lr] = bv.z; Bs[lc + 3][lr] = bv.w;
        __syncthreads();

        #pragma unroll
        for (int k = 0; k < 16; k++) {
            float a[4], b[4];
            #pragma unroll
            for (int i = 0; i < 4; i++) a[i] = As[k][ty + 16 * i];
            #pragma unroll
            for (int j = 0; j < 4; j++) b[j] = Bs[k][tx + 16 * j];
            #pragma unroll
            for (int i = 0; i < 4; i++)
                #pragma unroll
                for (int j = 0; j < 4; j++)
                    acc[i][j] += a[i] * b[j];
        }
        __syncthreads();
    }

    #pragma unroll
    for (int i = 0; i < 4; i++) {
        const int m = m0 + ty + 16 * i;
        #pragma unroll
        for (int j = 0; j < 4; j++) {
            const int n = n0 + tx + 16 * j;
            C[(size_t)m * ldc + n] = acc[i][j] * scale;
        }
    }
}

// ---------------------------------------------------------------------------
// Scores: S[z, q, k] = 0.125 * sum_d Q[b, q, h*64+d] * K[b, k, h*64+d]
// z = b*16 + h. grid = (32 ktile, 32 qtile, 32 bh), 256 threads.
// ---------------------------------------------------------------------------
__global__ void scores_kernel(const float* __restrict__ Q,
                              const float* __restrict__ Kmat,
                              float* __restrict__ S)
{
    __shared__ float As[16][65];
    __shared__ float Bs[16][65];

    const int z = blockIdx.z;
    const int b = z >> 4, h = z & 15;
    const float* A  = Q    + (size_t)b * SEQ * D_MODEL + h * DK;
    const float* Bm = Kmat + (size_t)b * SEQ * D_MODEL + h * DK;
    float* C = S + (size_t)z * SEQ * SEQ;

    const int tid = threadIdx.x;
    const int tx = tid & 15;
    const int ty = tid >> 4;
    const int m0 = blockIdx.y * 64;
    const int n0 = blockIdx.x * 64;

    float acc[4][4] = {};

    const int lr = tid >> 2;
    const int lc = (tid & 3) * 4;

    #pragma unroll
    for (int k0 = 0; k0 < DK; k0 += 16) {
        float4 av = *reinterpret_cast<const float4*>(A  + (size_t)(m0 + lr) * D_MODEL + k0 + lc);
        float4 bv = *reinterpret_cast<const float4*>(Bm + (size_t)(n0 + lr) * D_MODEL + k0 + lc);
        As[lc + 0][lr] = av.x; As[lc + 1][lr] = av.y; As[lc + 2][lr] = av.z; As[lc + 3][lr] = av.w;
        Bs[lc + 0][lr] = bv.x; Bs[lc + 1][lr] = bv.y; Bs[lc + 2][lr] = bv.z; Bs[lc + 3][lr] = bv.w;
        __syncthreads();

        #pragma unroll
        for (int k = 0; k < 16; k++) {
            float a[4], bb[4];
            #pragma unroll
            for (int i = 0; i < 4; i++) a[i] = As[k][ty + 16 * i];
            #pragma unroll
            for (int j = 0; j < 4; j++) bb[j] = Bs[k][tx + 16 * j];
            #pragma unroll
            for (int i = 0; i < 4; i++)
                #pragma unroll
                for (int j = 0; j < 4; j++)
                    acc[i][j] += a[i] * bb[j];
        }
        __syncthreads();
    }

    #pragma unroll
    for (int i = 0; i < 4; i++) {
        const int m = m0 + ty + 16 * i;
        #pragma unroll
        for (int j = 0; j < 4; j++) {
            const int n = n0 + tx + 16 * j;
            C[(size_t)m * SEQ + n] = acc[i][j] * 0.125f;  // 1/sqrt(64)
        }
    }
}

// ---------------------------------------------------------------------------
// Softmax in-place over rows of S (row length SEQ=2048).
// One block (256 threads) per row, 8 elements per thread kept in registers.
// ---------------------------------------------------------------------------
__global__ void softmax_kernel(float* __restrict__ S)
{
    float* row = S + (size_t)blockIdx.x * SEQ;
    const int tid = threadIdx.x;

    float v[8];
    float m = -1e30f;
    #pragma unroll
    for (int i = 0; i < 8; i++) {
        v[i] = row[tid + i * 256];
        m = fmaxf(m, v[i]);
    }
    #pragma unroll
    for (int o = 16; o; o >>= 1) m = fmaxf(m, __shfl_xor_sync(0xFFFFFFFFu, m, o));

    __shared__ float red[8];
    if ((tid & 31) == 0) red[tid >> 5] = m;
    __syncthreads();
    float bm = red[0];
    #pragma unroll
    for (int i = 1; i < 8; i++) bm = fmaxf(bm, red[i]);
    __syncthreads();

    float s = 0.f;
    #pragma unroll
    for (int i = 0; i < 8; i++) {
        v[i] = __expf(v[i] - bm);
        s += v[i];
    }
    #pragma unroll
    for (int o = 16; o; o >>= 1) s += __shfl_xor_sync(0xFFFFFFFFu, s, o);
    if ((tid & 31) == 0) red[tid >> 5] = s;
    __syncthreads();
    float bs = red[0];
    #pragma unroll
    for (int i = 1; i < 8; i++) bs += red[i];

    const float inv = 1.0f / bs;
    #pragma unroll
    for (int i = 0; i < 8; i++) row[tid + i * 256] = v[i] * inv;
}

// ---------------------------------------------------------------------------
// P·V: O[b, q, h*64+d] = sum_k P[z, q, k] * V[b, k, h*64+d]
// NN GEMM with K=2048. grid = (1, 32 qtile, 32 bh), 256 threads.
// ---------------------------------------------------------------------------
__global__ void pv_kernel(const float* __restrict__ P,
                          const float* __restrict__ V,
                          float* __restrict__ O)
{
    __shared__ float As[16][65];
    __shared__ float Bs[16][68];

    const int z = blockIdx.z;
    const int b = z >> 4, h = z & 15;
    const float* A  = P + (size_t)z * SEQ * SEQ;
    const float* Bp = V + (size_t)b * SEQ * D_MODEL + h * DK;
    float* C = O + (size_t)b * SEQ * D_MODEL + h * DK;

    const int tid = threadIdx.x;
    const int tx = tid & 15;
    const int ty = tid >> 4;
    const int m0 = blockIdx.y * 64;

    float acc[4][4] = {};

    const int lr = tid >> 2;        // A-tile row 0..63
    const int lc = (tid & 3) * 4;   // A-tile k-col 0,4,8,12
    const int br = tid >> 4;        // B-tile k-row 0..15
    const int bc = (tid & 15) * 4;  // B-tile n-col 0..60

    for (int k0 = 0; k0 < SEQ; k0 += 16) {
        float4 av = *reinterpret_cast<const float4*>(A + (size_t)(m0 + lr) * SEQ + k0 + lc);
        As[lc + 0][lr] = av.x; As[lc + 1][lr] = av.y; As[lc + 2][lr] = av.z; As[lc + 3][lr] = av.w;
        float4 bv = *reinterpret_cast<const float4*>(Bp + (size_t)(k0 + br) * D_MODEL + bc);
        Bs[br][bc + 0] = bv.x; Bs[br][bc + 1] = bv.y; Bs[br][bc + 2] = bv.z; Bs[br][bc + 3] = bv.w;
        __syncthreads();

        #pragma unroll
        for (int k = 0; k < 16; k++) {
            float a[4], bb[4];
            #pragma unroll
            for (int i = 0; i < 4; i++) a[i] = As[k][ty + 16 * i];
            #pragma unroll
            for (int j = 0; j < 4; j++) bb[j] = Bs[k][tx + 16 * j];
            #pragma unroll
            for (int i = 0; i < 4; i++)
                #pragma unroll
                for (int j = 0; j < 4; j++)
                    acc[i][j] += a[i] * bb[j];
        }
        __syncthreads();
    }

    #pragma unroll
    for (int i = 0; i < 4; i++) {
        const int m = m0 + ty + 16 * i;
        #pragma unroll
        for (int j = 0; j < 4; j++) {
            const int n = tx + 16 * j;  // 0..63 = head dim
            C[(size_t)m * D_MODEL + n] = acc[i][j];
        }
    }
}

// ---------------------------------------------------------------------------
// Host launcher
// ---------------------------------------------------------------------------
extern "C" void kernel_launch(void* const* d_in, const int* in_sizes, int n_in,
                              void* d_out, int out_size)
{
    const float* x  = (const float*)d_in[0];
    const float* Wq = (const float*)d_in[1];
    const float* Wk = (const float*)d_in[2];
    const float* Wv = (const float*)d_in[3];
    const float* Wo = (const float*)d_in[4];
    float* out = (float*)d_out;

    float *pQ, *pK, *pV, *pO, *pSfb;
    cudaGetSymbolAddress((void**)&pQ, g_Q);
    cudaGetSymbolAddress((void**)&pK, g_K);
    cudaGetSymbolAddress((void**)&pV, g_V);
    cudaGetSymbolAddress((void**)&pO, g_O);
    cudaGetSymbolAddress((void**)&pSfb, g_S_fallback);

    const size_t projN = (size_t)MTOT * D_MODEL;                 // 4,194,304
    const size_t attnN = (size_t)BATCH * N_HEADS * SEQ * SEQ;    // 134,217,728
    // Output layout: [out (projN floats)] [attn_weights (attnN floats)]
    float* S = ((size_t)out_size >= projN + attnN) ? (out + projN) : pSfb;

    dim3 blk(256);

    // QKV projections: [4096,1024] = x[4096,1024] @ W[1024,1024]^T
    dim3 gproj(D_MODEL / 64, MTOT / 64);
    gemm_nt<<<gproj, blk>>>(x, Wq, pQ, D_MODEL, D_MODEL, D_MODEL, D_MODEL, 1.0f);
    gemm_nt<<<gproj, blk>>>(x, Wk, pK, D_MODEL, D_MODEL, D_MODEL, D_MODEL, 1.0f);
    gemm_nt<<<gproj, blk>>>(x, Wv, pV, D_MODEL, D_MODEL, D_MODEL, D_MODEL, 1.0f);

    // Scores: per (b,h), S = 0.125 * Q_h K_h^T
    dim3 gscore(SEQ / 64, SEQ / 64, BATCH * N_HEADS);
    scores_kernel<<<gscore, blk>>>(pQ, pK, S);

    // Softmax over each of the 65536 rows
    softmax_kernel<<<BATCH * N_HEADS * SEQ, 256>>>(S);

    // O = P @ V  (per head)
    dim3 gpv(1, SEQ / 64, BATCH * N_HEADS);
    pv_kernel<<<gpv, blk>>>(S, pV, pO);

    // Final projection: out = O @ Wo^T
    gemm_nt<<<gproj, blk>>>(pO, Wo, out, D_MODEL, D_MODEL, D_MODEL, D_MODEL, 1.0f);
}

// round 3
// speedup vs baseline: 1.8203x; 1.8203x over previous
#include <cuda_runtime.h>
#include <mma.h>
#include <cstdint>

using namespace nvcuda;

#define D_MODEL 1024
#define N_HEADS 16
#define DK      64
#define BATCH   2
#define SEQ     2048
#define MTOT    (BATCH*SEQ)

// ------------------------- scratch (no allocs allowed) ----------------------
__device__ float g_xt[(size_t)MTOT * D_MODEL];          // tf32-rounded x
__device__ float g_wt[(size_t)4 * D_MODEL * D_MODEL];   // tf32-rounded Wq,Wk,Wv,Wo
__device__ float g_Q [(size_t)MTOT * D_MODEL];
__device__ float g_K [(size_t)MTOT * D_MODEL];
__device__ float g_V [(size_t)MTOT * D_MODEL];
__device__ float g_Vt[(size_t)MTOT * D_MODEL];          // [b,h][dk][seq]
__device__ float g_O [(size_t)MTOT * D_MODEL];

// ------------------------- helpers ------------------------------------------
__device__ __forceinline__ float tf32r(float x) {
    uint32_t u;
    asm("cvt.rna.tf32.f32 %0, %1;" : "=r"(u) : "f"(x));
    return __uint_as_float(u);
}
__device__ __forceinline__ uint32_t smem_u32(const void* p) {
    uint32_t a;
    asm("{ .reg .u64 t; cvta.to.shared.u64 t, %1; cvt.u32.u64 %0, t; }" : "=r"(a) : "l"(p));
    return a;
}
__device__ __forceinline__ void cp16(uint32_t dst, const void* src) {
    asm volatile("cp.async.cg.shared.global [%0], [%1], 16;" :: "r"(dst), "l"(src));
}
__device__ __forceinline__ void cp_commit() {
    asm volatile("cp.async.commit_group;" ::: "memory");
}
template<int N> __device__ __forceinline__ void cp_wait() {
    asm volatile("cp.async.wait_group %0;" :: "n"(N) : "memory");
}

// ------------------------- tf32 WMMA GEMM -----------------------------------
// C[m,n] = scale * sum_k A[m,k] * B[n,k]  (A,B K-major), TILE_M=128, BK=32.
// 256 threads = 8 warps in 2(M) x 4(N); warp tile = 64 x (TILE_N/4).
#define NSTAGE 3
#define BK     32
#define LDS    40   // smem row stride (floats)

template<int TILE_N, bool ROUND>
__global__ void __launch_bounds__(256)
wmma_gemm(const float* __restrict__ A, const float* __restrict__ B, float* __restrict__ C,
          int K, int lda, int ldb, int ldc, float scale,
          long long sAhi, long long sAlo, long long sBhi, long long sBlo,
          long long sChi, long long sClo)
{
    constexpr int AELEM = 128 * LDS;
    constexpr int BELEM = TILE_N * LDS;
    constexpr int NB    = TILE_N / 64;   // wmma n-tiles per warp

    extern __shared__ float sm[];
    float* sA = sm;
    float* sB = sm + (size_t)NSTAGE * AELEM;

    const int tid = threadIdx.x;
    const int wid = tid >> 5;
    const int warp_m = wid & 1;          // 0..1
    const int warp_n = wid >> 1;         // 0..3

    const int z  = blockIdx.z;
    const int zh = z >> 4, zl = z & 15;
    const float* Ao = A + (size_t)zh * sAhi + (size_t)zl * sAlo;
    const float* Bo = B + (size_t)zh * sBhi + (size_t)zl * sBlo;
    float*       Co = C + (size_t)zh * sChi + (size_t)zl * sClo;

    const int m0 = blockIdx.y * 128;
    const int n0 = blockIdx.x * TILE_N;
    const int nch = K >> 5;

    wmma::fragment<wmma::accumulator, 16, 16, 8, float> cf[4][NB];
    #pragma unroll
    for (int i = 0; i < 4; i++)
        #pragma unroll
        for (int j = 0; j < NB; j++)
            wmma::fill_fragment(cf[i][j], 0.0f);

    // async tile loader: chunk c into stage s
    auto load = [&](int s, int c) {
        const int k0 = c * BK;
        uint32_t aB = smem_u32(sA + (size_t)s * AELEM);
        uint32_t bB = smem_u32(sB + (size_t)s * BELEM);
        #pragma unroll
        for (int j = 0; j < 4; j++) {
            int f = tid + j * 256, r = f >> 3, q = f & 7;
            cp16(aB + (uint32_t)(r * LDS + q * 4) * 4,
                 Ao + (size_t)(m0 + r) * lda + k0 + q * 4);
        }
        #pragma unroll
        for (int j = 0; j < TILE_N / 32; j++) {
            int f = tid + j * 256, r = f >> 3, q = f & 7;
            cp16(bB + (uint32_t)(r * LDS + q * 4) * 4,
                 Bo + (size_t)(n0 + r) * ldb + k0 + q * 4);
        }
        cp_commit();
    };

    // prologue: fill NSTAGE-1 stages
    const int P0 = (nch < NSTAGE - 1) ? nch : NSTAGE - 1;
    for (int c = 0; c < P0; c++) load(c, c);

    for (int c = 0; c < nch; c++) {
        const int s = c % NSTAGE;
        if (c + NSTAGE - 1 < nch) cp_wait<NSTAGE - 2>(); else cp_wait<0>();
        __syncthreads();
        if (c + NSTAGE - 1 < nch) load((c + NSTAGE - 1) % NSTAGE, c + NSTAGE - 1);

        const float* As = sA + (size_t)s * AELEM + warp_m * 64 * LDS;
        const float* Bs = sB + (size_t)s * BELEM + warp_n * (TILE_N / 4) * LDS;
        #pragma unroll
        for (int kc = 0; kc < 4; kc++) {
            wmma::fragment<wmma::matrix_a, 16, 16, 8, wmma::precision::tf32, wmma::row_major> af[4];
            wmma::fragment<wmma::matrix_b, 16, 16, 8, wmma::precision::tf32, wmma::col_major> bf[NB];
            #pragma unroll
            for (int i = 0; i < 4; i++)
                wmma::load_matrix_sync(af[i], As + i * 16 * LDS + kc * 8, LDS);
            #pragma unroll
            for (int j = 0; j < NB; j++)
                wmma::load_matrix_sync(bf[j], Bs + j * 16 * LDS + kc * 8, LDS);
            #pragma unroll
            for (int i = 0; i < 4; i++)
                #pragma unroll
                for (int j = 0; j < NB; j++)
                    wmma::mma_sync(cf[i][j], af[i], bf[j], cf[i][j]);
        }
        __syncthreads();
    }

    // epilogue: scale, optional tf32 rounding, direct global store
    #pragma unroll
    for (int i = 0; i < 4; i++) {
        #pragma unroll
        for (int j = 0; j < NB; j++) {
            #pragma unroll
            for (int e = 0; e < 8; e++) {
                float v = cf[i][j].x[e] * scale;
                if (ROUND) v = tf32r(v);
                cf[i][j].x[e] = v;
            }
            float* Cp = Co + (size_t)(m0 + warp_m * 64 + i * 16) * ldc
                           + n0 + warp_n * (TILE_N / 4) + j * 16;
            wmma::store_matrix_sync(Cp, cf[i][j], ldc, wmma::mem_row_major);
        }
    }
}

// ------------------------- aux kernels ---------------------------------------
__global__ void cvt_tf32_kernel(const float4* __restrict__ src, float4* __restrict__ dst, int n4)
{
    int i = blockIdx.x * blockDim.x + threadIdx.x;
    if (i < n4) {
        float4 v = src[i];
        v.x = tf32r(v.x); v.y = tf32r(v.y); v.z = tf32r(v.z); v.w = tf32r(v.w);
        dst[i] = v;
    }
}

// V [b, s, h*64+d] -> Vt [(b*16+h), d, s]
__global__ void transpose_v_kernel(const float* __restrict__ V, float* __restrict__ Vt)
{
    __shared__ float tile[32][33];
    const int z = blockIdx.z, b = z >> 4, h = z & 15;
    const int s0 = blockIdx.x * 32, d0 = blockIdx.y * 32;
    const int tx = threadIdx.x, ty = threadIdx.y;
    #pragma unroll
    for (int i = 0; i < 4; i++) {
        int s = s0 + ty + 8 * i;
        tile[ty + 8 * i][tx] = V[(size_t)(b * SEQ + s) * D_MODEL + h * DK + d0 + tx];
    }
    __syncthreads();
    #pragma unroll
    for (int i = 0; i < 4; i++) {
        int d = d0 + ty + 8 * i;
        Vt[(size_t)z * DK * SEQ + (size_t)d * SEQ + s0 + tx] = tile[tx][ty + 8 * i];
    }
}

__global__ void softmax_kernel(float* __restrict__ S)
{
    float* row = S + (size_t)blockIdx.x * SEQ;
    const int tid = threadIdx.x;
    float v[8];
    float m = -1e30f;
    #pragma unroll
    for (int i = 0; i < 8; i++) { v[i] = row[tid + i * 256]; m = fmaxf(m, v[i]); }
    #pragma unroll
    for (int o = 16; o; o >>= 1) m = fmaxf(m, __shfl_xor_sync(0xFFFFFFFFu, m, o));
    __shared__ float red[8];
    if ((tid & 31) == 0) red[tid >> 5] = m;
    __syncthreads();
    float bm = red[0];
    #pragma unroll
    for (int i = 1; i < 8; i++) bm = fmaxf(bm, red[i]);
    __syncthreads();
    float s = 0.f;
    #pragma unroll
    for (int i = 0; i < 8; i++) { v[i] = __expf(v[i] - bm); s += v[i]; }
    #pragma unroll
    for (int o = 16; o; o >>= 1) s += __shfl_xor_sync(0xFFFFFFFFu, s, o);
    if ((tid & 31) == 0) red[tid >> 5] = s;
    __syncthreads();
    float bs = red[0];
    #pragma unroll
    for (int i = 1; i < 8; i++) bs += red[i];
    const float inv = 1.0f / bs;
    #pragma unroll
    for (int i = 0; i < 8; i++) row[tid + i * 256] = tf32r(v[i] * inv);
}

// ------------------------- host ----------------------------------------------
extern "C" void kernel_launch(void* const* d_in, const int* in_sizes, int n_in,
                              void* d_out, int out_size)
{
    const float* x  = (const float*)d_in[0];
    const float* Wq = (const float*)d_in[1];
    const float* Wk = (const float*)d_in[2];
    const float* Wv = (const float*)d_in[3];
    const float* Wo = (const float*)d_in[4];
    float* out = (float*)d_out;

    float *pxt, *pwt, *pQ, *pK, *pV, *pVt, *pO;
    cudaGetSymbolAddress((void**)&pxt, g_xt);
    cudaGetSymbolAddress((void**)&pwt, g_wt);
    cudaGetSymbolAddress((void**)&pQ,  g_Q);
    cudaGetSymbolAddress((void**)&pK,  g_K);
    cudaGetSymbolAddress((void**)&pV,  g_V);
    cudaGetSymbolAddress((void**)&pVt, g_Vt);
    cudaGetSymbolAddress((void**)&pO,  g_O);

    const size_t projN = (size_t)MTOT * D_MODEL;
    float* S = out + projN;   // attn_weights region of d_out
    const size_t M2 = (size_t)D_MODEL * D_MODEL;

    const int smem128 = NSTAGE * (128 + 128) * LDS * 4;   // 122880 B
    const int smem64  = NSTAGE * (128 +  64) * LDS * 4;   //  92160 B
    cudaFuncSetAttribute(wmma_gemm<128, true >, cudaFuncAttributeMaxDynamicSharedMemorySize, smem128);
    cudaFuncSetAttribute(wmma_gemm<128, false>, cudaFuncAttributeMaxDynamicSharedMemorySize, smem128);
    cudaFuncSetAttribute(wmma_gemm< 64, true >, cudaFuncAttributeMaxDynamicSharedMemorySize, smem64);

    // 1) round inputs to tf32 (so HMMA truncation is exact)
    cvt_tf32_kernel<<<(int)(projN / 4 + 255) / 256, 256>>>((const float4*)x, (float4*)pxt, (int)(projN / 4));
    cvt_tf32_kernel<<<(int)(M2 / 4 + 255) / 256, 256>>>((const float4*)Wq, (float4*)(pwt + 0 * M2), (int)(M2 / 4));
    cvt_tf32_kernel<<<(int)(M2 / 4 + 255) / 256, 256>>>((const float4*)Wk, (float4*)(pwt + 1 * M2), (int)(M2 / 4));
    cvt_tf32_kernel<<<(int)(M2 / 4 + 255) / 256, 256>>>((const float4*)Wv, (float4*)(pwt + 2 * M2), (int)(M2 / 4));
    cvt_tf32_kernel<<<(int)(M2 / 4 + 255) / 256, 256>>>((const float4*)Wo, (float4*)(pwt + 3 * M2), (int)(M2 / 4));

    // 2) projections Q/K/V = x @ W^T (tf32-rounded outputs)
    dim3 gproj(D_MODEL / 128, MTOT / 128, 1);
    wmma_gemm<128, true><<<gproj, 256, smem128>>>(pxt, pwt + 0 * M2, pQ, D_MODEL, D_MODEL, D_MODEL, D_MODEL,
                                                  1.0f, 0, 0, 0, 0, 0, 0);
    wmma_gemm<128, true><<<gproj, 256, smem128>>>(pxt, pwt + 1 * M2, pK, D_MODEL, D_MODEL, D_MODEL, D_MODEL,
                                                  1.0f, 0, 0, 0, 0, 0, 0);
    wmma_gemm<128, true><<<gproj, 256, smem128>>>(pxt, pwt + 2 * M2, pV, D_MODEL, D_MODEL, D_MODEL, D_MODEL,
                                                  1.0f, 0, 0, 0, 0, 0, 0);

    // 3) transpose V per head
    transpose_v_kernel<<<dim3(SEQ / 32, DK / 32, BATCH * N_HEADS), dim3(32, 8)>>>(pV, pVt);

    // 4) scores S = 0.125 * Q K^T per head
    dim3 gsc(SEQ / 128, SEQ / 128, BATCH * N_HEADS);
    wmma_gemm<128, false><<<gsc, 256, smem128>>>(pQ, pK, S, DK, D_MODEL, D_MODEL, SEQ, 0.125f,
                                                 (long long)SEQ * D_MODEL, DK,
                                                 (long long)SEQ * D_MODEL, DK,
                                                 (long long)16 * SEQ * SEQ, (long long)SEQ * SEQ);

    // 5) softmax rows (writes tf32-rounded P = attn_weights output)
    softmax_kernel<<<BATCH * N_HEADS * SEQ, 256>>>(S);

    // 6) O = P @ Vt^T per head (N=64)
    dim3 gpv(1, SEQ / 128, BATCH * N_HEADS);
    wmma_gemm<64, true><<<gpv, 256, smem64>>>(S, pVt, pO, SEQ, SEQ, SEQ, D_MODEL, 1.0f,
                                              (long long)16 * SEQ * SEQ, (long long)SEQ * SEQ,
                                              (long long)16 * DK * SEQ, (long long)DK * SEQ,
                                              (long long)SEQ * D_MODEL, DK);

    // 7) out = O @ Wo^T (full fp32 store)
    wmma_gemm<128, false><<<gproj, 256, smem128>>>(pO, pwt + 3 * M2, out, D_MODEL, D_MODEL, D_MODEL, D_MODEL,
                                                   1.0f, 0, 0, 0, 0, 0, 0);
}